// round 16
// baseline (speedup 1.0000x reference)
#include <cuda_runtime.h>
#include <cuda_bf16.h>
#include <math.h>
#include <stdint.h>

#define NTOT 16384
#define DDIM 256
#define KCB  8192
#define GATHER_BLOCKS 4096
#define NCAND 8
#define NUNITS 1024          // 128 M-blocks x 8 kslabs
#define NCTA   148

#define LOSS_OFF (NTOT*DDIM)
#define IDX_OFF  (NTOT*DDIM + 1)
#define PPL_OFF  (NTOT*DDIM + 1 + NTOT)
#define OUT_FULL (NTOT*DDIM + 2 + NTOT)

__device__ __align__(16) uint8_t g_z8[(size_t)NTOT * DDIM];
__device__ __align__(16) uint8_t g_cb8[(size_t)KCB * DDIM];
__device__ float g_e2f[KCB];
__device__ float g_csc[KCB];
__device__ float g_zsc[NTOT];
__device__ float g_cpd[(size_t)NTOT * 64];   // per-(row,kslab) top-8 dists
__device__ int   g_cpi[(size_t)NTOT * 64];   // per-(row,kslab) top-8 codes
__device__ int   g_cand[(size_t)NTOT * NCAND];
__device__ int   g_idx[NTOT];
__device__ float g_partial[GATHER_BLOCKS];
__device__ int   g_count = 0;

// ---------------------------------------------------------------------------
// helpers
// ---------------------------------------------------------------------------
__device__ __forceinline__ uint32_t smem_u32(const void* p) {
    uint32_t a;
    asm("{ .reg .u64 t; cvta.to.shared.u64 t, %1; cvt.u32.u64 %0, t; }"
        : "=r"(a) : "l"(p));
    return a;
}
#define CP_ASYNC16(dst, src) \
    asm volatile("cp.async.cg.shared.global [%0], [%1], 16;" :: "r"(dst), "l"(src))
#define CP_COMMIT() asm volatile("cp.async.commit_group;" ::: "memory")
#define CP_WAIT(n)  asm volatile("cp.async.wait_group %0;" :: "n"(n) : "memory")

__device__ __forceinline__ void ldsm_x4(uint32_t* r, uint32_t addr) {
    asm volatile("ldmatrix.sync.aligned.m8n8.x4.shared.b16 {%0,%1,%2,%3}, [%4];"
                 : "=r"(r[0]), "=r"(r[1]), "=r"(r[2]), "=r"(r[3]) : "r"(addr));
}
__device__ __forceinline__ void imma16832(int* d, const uint32_t* a,
                                          uint32_t b0, uint32_t b1) {
    asm volatile(
        "mma.sync.aligned.m16n8k32.row.col.s32.s8.s8.s32 "
        "{%0,%1,%2,%3}, {%4,%5,%6,%7}, {%8,%9}, {%0,%1,%2,%3};"
        : "+r"(d[0]), "+r"(d[1]), "+r"(d[2]), "+r"(d[3])
        : "r"(a[0]), "r"(a[1]), "r"(a[2]), "r"(a[3]), "r"(b0), "r"(b1));
}
__device__ __forceinline__ void upd(float& b1, int& i1, float& b2, int& i2,
                                    float d, int code) {
    if (d < b2) {
        if (d < b1) { b2 = b1; i2 = i1; b1 = d; i1 = code; }
        else        { b2 = d; i2 = code; }
    }
}
__device__ __forceinline__ uint32_t pack_s8x4(int q0, int q1, int q2, int q3) {
    return (uint32_t)(q0 & 255) | ((uint32_t)(q1 & 255) << 8)
         | ((uint32_t)(q2 & 255) << 16) | ((uint32_t)(q3 & 255) << 24);
}

// ---------------------------------------------------------------------------
// Kernel 1: per-row int8 quantization of z,cb; exact fp32 e2; last block: ppl
// ---------------------------------------------------------------------------
__global__ void vq_convert_kernel(const float* __restrict__ z,
                                  const float* __restrict__ cb,
                                  const float* __restrict__ ema,
                                  float* __restrict__ out, int out_size) {
    int w    = (blockIdx.x * blockDim.x + threadIdx.x) >> 5;
    int lane = threadIdx.x & 31;
    if (w < KCB) {
        const float4* src = (const float4*)(cb + (size_t)w * DDIM);
        float4 v0 = src[lane * 2], v1 = src[lane * 2 + 1];
        float e2 = v0.x*v0.x + v0.y*v0.y + v0.z*v0.z + v0.w*v0.w
                 + v1.x*v1.x + v1.y*v1.y + v1.z*v1.z + v1.w*v1.w;
        float ma = fmaxf(fmaxf(fmaxf(fabsf(v0.x), fabsf(v0.y)), fmaxf(fabsf(v0.z), fabsf(v0.w))),
                         fmaxf(fmaxf(fabsf(v1.x), fabsf(v1.y)), fmaxf(fabsf(v1.z), fabsf(v1.w))));
#pragma unroll
        for (int o = 16; o > 0; o >>= 1) {
            e2 += __shfl_xor_sync(0xffffffffu, e2, o);
            ma  = fmaxf(ma, __shfl_xor_sync(0xffffffffu, ma, o));
        }
        float inv = 127.f / ma;
        uint2 o8;
        o8.x = pack_s8x4(__float2int_rn(v0.x*inv), __float2int_rn(v0.y*inv),
                         __float2int_rn(v0.z*inv), __float2int_rn(v0.w*inv));
        o8.y = pack_s8x4(__float2int_rn(v1.x*inv), __float2int_rn(v1.y*inv),
                         __float2int_rn(v1.z*inv), __float2int_rn(v1.w*inv));
        ((uint2*)(g_cb8 + (size_t)w * DDIM))[lane] = o8;
        if (lane == 0) { g_e2f[w] = e2; g_csc[w] = ma / 127.f; }
    } else if (w < KCB + NTOT) {
        int r = w - KCB;
        const float4* src = (const float4*)(z + (size_t)r * DDIM);
        float4 v0 = src[lane * 2], v1 = src[lane * 2 + 1];
        float ma = fmaxf(fmaxf(fmaxf(fabsf(v0.x), fabsf(v0.y)), fmaxf(fabsf(v0.z), fabsf(v0.w))),
                         fmaxf(fmaxf(fabsf(v1.x), fabsf(v1.y)), fmaxf(fabsf(v1.z), fabsf(v1.w))));
#pragma unroll
        for (int o = 16; o > 0; o >>= 1)
            ma = fmaxf(ma, __shfl_xor_sync(0xffffffffu, ma, o));
        float inv = 127.f / ma;
        uint2 o8;
        o8.x = pack_s8x4(__float2int_rn(v0.x*inv), __float2int_rn(v0.y*inv),
                         __float2int_rn(v0.z*inv), __float2int_rn(v0.w*inv));
        o8.y = pack_s8x4(__float2int_rn(v1.x*inv), __float2int_rn(v1.y*inv),
                         __float2int_rn(v1.z*inv), __float2int_rn(v1.w*inv));
        ((uint2*)(g_z8 + (size_t)r * DDIM))[lane] = o8;
        if (lane == 0) g_zsc[r] = ma / 127.f;
    } else {
        // perplexity block (depends only on ema)
        __shared__ float r1[256], r2[256];
        const int t = threadIdx.x;
        float sc = 0.f, scl = 0.f;
        for (int k = t; k < KCB; k += 256) {
            float c = ema[k];
            if (k == 2 || k == 3) c = 0.f;
            c = fmaxf(c, 1e-5f);
            sc  += c;
            scl += c * logf(c);
        }
        r1[t] = sc; r2[t] = scl;
        __syncthreads();
#pragma unroll
        for (int o = 128; o > 0; o >>= 1) {
            if (t < o) { r1[t] += r1[t + o]; r2[t] += r2[t + o]; }
            __syncthreads();
        }
        if (t == 0 && out_size >= OUT_FULL) {
            float T = r1[0] + 1e-5f;
            float entropy = logf(T) * (r1[0] / T) - r2[0] / T;
            out[PPL_OFF] = expf(entropy);
        }
    }
}

// ---------------------------------------------------------------------------
// Kernel 2: persistent coarse IMMA GEMM. 148 CTAs, unit = (M-block, kslab-8).
// smem: z 32KB @0, cb 2x32KB @32768, e2 2x512 @98304, csc 2x512 @99328
// ---------------------------------------------------------------------------
#define ZS_OFF 0
#define CB_OFF 32768
#define E2_OFF 98304
#define SC_OFF 99328
#define DSMEM  (100352 + 1024)

__device__ __forceinline__ void prefetch_cb(uint32_t sb, int buf, int chunk, int t) {
    const char* csrc = (const char*)(g_cb8 + (size_t)chunk * 128 * DDIM);
    uint32_t cbase = sb + CB_OFF + (uint32_t)buf * 32768u;
#pragma unroll
    for (int i = 0; i < 8; i++) {
        int id = t + i * 256, r = id >> 4, c = id & 15;
        uint32_t dst = cbase + (uint32_t)r * 256u
                     + ((uint32_t)((c & 8) | ((c ^ r) & 7)) << 4);
        CP_ASYNC16(dst, csrc + (size_t)r * 256 + c * 16);
    }
    if (t < 32) {
        uint32_t dst = sb + E2_OFF + (uint32_t)buf * 512u + (uint32_t)t * 16u;
        CP_ASYNC16(dst, (const char*)(g_e2f + chunk * 128) + t * 16);
    } else if (t < 64) {
        int tt = t - 32;
        uint32_t dst = sb + SC_OFF + (uint32_t)buf * 512u + (uint32_t)tt * 16u;
        CP_ASYNC16(dst, (const char*)(g_csc + chunk * 128) + tt * 16);
    }
}

__global__ void __launch_bounds__(256, 1) vq_coarse_kernel() {
    extern __shared__ __align__(16) char dsm[];
    const uint32_t sb = (smem_u32(dsm) + 1023u) & ~1023u;
    const int t  = threadIdx.x;
    const int l  = t & 31;
    const int wid = t >> 5;
    const int wm = wid >> 2, wn = wid & 3;

    // per-thread constant address components (unit-independent)
    uint32_t abase[4], ar7[4];
#pragma unroll
    for (int i = 0; i < 4; i++) {
        int ar = wm * 64 + i * 16 + (l & 15);
        abase[i] = sb + ZS_OFF + (uint32_t)ar * 256u;
        ar7[i]   = (uint32_t)(ar & 7);
    }
    const uint32_t ahalf = (uint32_t)(l >> 4);
    uint32_t boff[2], br7[2];
#pragma unroll
    for (int p = 0; p < 2; p++) {
        int br = wn * 32 + p * 16 + ((l >> 4) & 1) * 8 + (l & 7);
        boff[p] = (uint32_t)br * 256u;
        br7[p]  = (uint32_t)(br & 7);
    }
    const uint32_t bhalf = (uint32_t)((l >> 3) & 1);
    const int nl0 = wn * 32 + (l & 3) * 2;

    for (int u = blockIdx.x; u < NUNITS; u += NCTA) {
        const int mb = u >> 3, ks = u & 7;
        const int m0 = mb * 128;
        const int c0 = ks * 8;

        // ---- z tile + first two cb chunks ----
        {
            const char* zsrc = (const char*)(g_z8 + (size_t)m0 * DDIM);
#pragma unroll
            for (int i = 0; i < 8; i++) {
                int id = t + i * 256, r = id >> 4, c = id & 15;
                uint32_t dst = sb + ZS_OFF + (uint32_t)r * 256u
                             + ((uint32_t)((c & 8) | ((c ^ r) & 7)) << 4);
                CP_ASYNC16(dst, zsrc + (size_t)r * 256 + c * 16);
            }
            prefetch_cb(sb, 0, c0, t);
            CP_COMMIT();
            prefetch_cb(sb, 1, c0 + 1, t);
            CP_COMMIT();
        }

        // -2 * z row scale for this thread's 8 row-slots
        float szm2[8];
#pragma unroll
        for (int i = 0; i < 4; i++)
#pragma unroll
            for (int h = 0; h < 2; h++) {
                int m = wm * 64 + i * 16 + (l >> 2) + h * 8;
                szm2[i * 2 + h] = -2.f * g_zsc[m0 + m];
            }

        float bd1[8], bd2[8];
        int   bi1[8], bi2[8];
#pragma unroll
        for (int i = 0; i < 8; i++) { bd1[i] = 3.0e38f; bd2[i] = 3.0e38f; bi1[i] = 0; bi2[i] = 0; }

        for (int cc = 0; cc < 8; cc++) {
            const int c = c0 + cc;
            const int s = cc & 1;
            if (cc < 7) { CP_WAIT(1); } else { CP_WAIT(0); }
            __syncthreads();

            int acc[4][4][4];
#pragma unroll
            for (int i = 0; i < 4; i++)
#pragma unroll
                for (int j = 0; j < 4; j++)
#pragma unroll
                    for (int q = 0; q < 4; q++) acc[i][j][q] = 0;

            const uint32_t cbB = sb + CB_OFF + (uint32_t)s * 32768u;
#pragma unroll
            for (int kk = 0; kk < 8; kk++) {
                const uint32_t cA = (uint32_t)(kk * 2) + ahalf;
                const uint32_t swA_hi = (cA & 8u) << 4;
                uint32_t a[4][4];
#pragma unroll
                for (int i = 0; i < 4; i++)
                    ldsm_x4(a[i], abase[i] + swA_hi + (((cA ^ ar7[i]) & 7u) << 4));
                const uint32_t cB = (uint32_t)(kk * 2) + bhalf;
                const uint32_t swB_hi = (cB & 8u) << 4;
                uint32_t b[2][4];
#pragma unroll
                for (int p = 0; p < 2; p++)
                    ldsm_x4(b[p], cbB + boff[p] + swB_hi + (((cB ^ br7[p]) & 7u) << 4));
#pragma unroll
                for (int i = 0; i < 4; i++)
#pragma unroll
                    for (int j = 0; j < 4; j++)
                        imma16832(acc[i][j], a[i], b[j >> 1][(j & 1) * 2], b[j >> 1][(j & 1) * 2 + 1]);
            }

            // epilogue: dist = e2 + (-2 sz sc) * idot, per-subset top-2
            const uint32_t e2b = sb + E2_OFF + (uint32_t)s * 512u;
            const uint32_t scb = sb + SC_OFF + (uint32_t)s * 512u;
#pragma unroll
            for (int j = 0; j < 4; j++) {
                const int nl = nl0 + j * 8;
                float e20, e21, sc0, sc1;
                asm("ld.shared.f32 %0, [%1];" : "=f"(e20) : "r"(e2b + (uint32_t)nl * 4u));
                asm("ld.shared.f32 %0, [%1];" : "=f"(e21) : "r"(e2b + (uint32_t)nl * 4u + 4u));
                asm("ld.shared.f32 %0, [%1];" : "=f"(sc0) : "r"(scb + (uint32_t)nl * 4u));
                asm("ld.shared.f32 %0, [%1];" : "=f"(sc1) : "r"(scb + (uint32_t)nl * 4u + 4u));
                const int code0 = c * 128 + nl, code1 = code0 + 1;
#pragma unroll
                for (int i = 0; i < 4; i++) {
                    float d0 = fmaf(szm2[i*2]   * sc0, (float)acc[i][j][0], e20);
                    float d1 = fmaf(szm2[i*2]   * sc1, (float)acc[i][j][1], e21);
                    float d2 = fmaf(szm2[i*2+1] * sc0, (float)acc[i][j][2], e20);
                    float d3 = fmaf(szm2[i*2+1] * sc1, (float)acc[i][j][3], e21);
                    upd(bd1[i*2],   bi1[i*2],   bd2[i*2],   bi2[i*2],   d0, code0);
                    upd(bd1[i*2],   bi1[i*2],   bd2[i*2],   bi2[i*2],   d1, code1);
                    upd(bd1[i*2+1], bi1[i*2+1], bd2[i*2+1], bi2[i*2+1], d2, code0);
                    upd(bd1[i*2+1], bi1[i*2+1], bd2[i*2+1], bi2[i*2+1], d3, code1);
                }
            }

            __syncthreads();                 // buf s fully consumed
            if (cc + 2 < 8) { prefetch_cb(sb, s, c + 2, t); CP_COMMIT(); }
        }

        // ---- per-unit merge: 32 subset-top-2 per row -> top-8, write slab slot ----
        __syncthreads();
        float* sdm = (float*)(dsm + (sb - smem_u32(dsm)));      // reuse z area
        int*   sim = (int*)(dsm + (sb - smem_u32(dsm)) + 16384);
        const int slot2 = (wn * 4 + (l & 3)) * 2;
#pragma unroll
        for (int i = 0; i < 4; i++) {
#pragma unroll
            for (int h = 0; h < 2; h++) {
                int m = wm * 64 + i * 16 + (l >> 2) + h * 8;
                sdm[m * 32 + slot2]     = bd1[i * 2 + h];
                sim[m * 32 + slot2]     = bi1[i * 2 + h];
                sdm[m * 32 + slot2 + 1] = bd2[i * 2 + h];
                sim[m * 32 + slot2 + 1] = bi2[i * 2 + h];
            }
        }
        __syncthreads();
        if (t < 128) {
            float td[NCAND]; int ti[NCAND];
#pragma unroll
            for (int q = 0; q < NCAND; q++) { td[q] = 3.0e38f; ti[q] = 0x7fffffff; }
            for (int e = 0; e < 32; e++) {
                float d = sdm[t * 32 + e];
                int  ix = sim[t * 32 + e];
                if (d < td[NCAND-1] || (d == td[NCAND-1] && ix < ti[NCAND-1])) {
                    int pos = NCAND - 1;
                    while (pos > 0 && (d < td[pos-1] || (d == td[pos-1] && ix < ti[pos-1]))) {
                        td[pos] = td[pos-1]; ti[pos] = ti[pos-1]; pos--;
                    }
                    td[pos] = d; ti[pos] = ix;
                }
            }
            size_t base = (size_t)(m0 + t) * 64 + ks * 8;
#pragma unroll
            for (int q = 0; q < NCAND; q++) {
                g_cpd[base + q] = td[q];
                g_cpi[base + q] = ti[q];
            }
        }
        __syncthreads();                     // before next unit overwrites z area
    }
}

// ---------------------------------------------------------------------------
// Kernel 2b: merge 8 kslab top-8 lists per row -> global top-8
// ---------------------------------------------------------------------------
__global__ void vq_merge_kernel() {
    const int row = blockIdx.x * 256 + threadIdx.x;
    const float* pd = g_cpd + (size_t)row * 64;
    const int*   pi = g_cpi + (size_t)row * 64;
    float td[NCAND]; int ti[NCAND];
#pragma unroll
    for (int q = 0; q < NCAND; q++) { td[q] = 3.0e38f; ti[q] = 0x7fffffff; }
    for (int e = 0; e < 64; e++) {
        float d = pd[e];
        int  ix = pi[e];
        if (d < td[NCAND-1] || (d == td[NCAND-1] && ix < ti[NCAND-1])) {
            int pos = NCAND - 1;
            while (pos > 0 && (d < td[pos-1] || (d == td[pos-1] && ix < ti[pos-1]))) {
                td[pos] = td[pos-1]; ti[pos] = ti[pos-1]; pos--;
            }
            td[pos] = d; ti[pos] = ix;
        }
    }
#pragma unroll
    for (int q = 0; q < NCAND; q++)
        g_cand[(size_t)row * NCAND + q] = ti[q];
}

// ---------------------------------------------------------------------------
// Kernel 3: exact fp32 rescore of 8 candidates per row (warp per row)
// ---------------------------------------------------------------------------
__global__ void __launch_bounds__(256) vq_rescore_kernel(const float* __restrict__ z,
                                                         const float* __restrict__ cb) {
    __shared__ __align__(16) float zs[8 * 256];
    const int t  = threadIdx.x;
    const int w  = t >> 5;
    const int l  = t & 31;
    const int r0 = blockIdx.x * 8;

    {
        const float4* src = (const float4*)(z + (size_t)r0 * DDIM);
        float4* dst = (float4*)zs;
        dst[t]       = src[t];
        dst[t + 256] = src[t + 256];
    }
    __syncthreads();

    const int row  = r0 + w;
    const int cand = g_cand[(size_t)row * NCAND + (l >> 2)];
    const int sub  = l & 3;
    const float4* cr = (const float4*)(cb + (size_t)cand * DDIM);
    const float*  zr = zs + w * 256;
    float s = 0.f;
#pragma unroll
    for (int k = 0; k < 16; k++) {
        int d4 = k * 4 + sub;
        float4 cv = cr[d4];
        float4 zv = *(const float4*)(zr + d4 * 4);
        float dx = zv.x - cv.x, dy = zv.y - cv.y, dz = zv.z - cv.z, dw = zv.w - cv.w;
        s += dx * dx + dy * dy + dz * dz + dw * dw;
    }
    s += __shfl_xor_sync(0xffffffffu, s, 1);
    s += __shfl_xor_sync(0xffffffffu, s, 2);

    float bd = 3.0e38f; int bi = 0x7fffffff;
#pragma unroll
    for (int q = 0; q < NCAND; q++) {
        float d  = __shfl_sync(0xffffffffu, s, q * 4);
        int   ix = __shfl_sync(0xffffffffu, cand, q * 4);
        if (d < bd || (d == bd && ix < bi)) { bd = d; bi = ix; }
    }
    if (l == 0) g_idx[row] = bi;
}

// ---------------------------------------------------------------------------
// Kernel 4: gather z_q, write indices, loss partials; last block reduces loss
// ---------------------------------------------------------------------------
__global__ void vq_gather_kernel(const float* __restrict__ z,
                                 const float* __restrict__ cb,
                                 float* __restrict__ out, int out_size) {
    __shared__ float red[256];
    __shared__ int   s_last;
    const int t    = threadIdx.x;
    const int base = blockIdx.x * 1024;
    const int e    = base + t * 4;
    const int row  = e >> 8;
    const int col  = e & 255;
    const int code = g_idx[row];

    float4 q  = *(const float4*)(cb + (size_t)code * DDIM + col);
    float4 zv = *(const float4*)(z + e);
    *(float4*)(out + e) = q;

    if (col == 0 && out_size >= OUT_FULL) out[IDX_OFF + row] = (float)code;

    float dx = q.x - zv.x, dy = q.y - zv.y, dz = q.z - zv.z, dw = q.w - zv.w;
    red[t] = dx * dx + dy * dy + dz * dz + dw * dw;
    __syncthreads();
#pragma unroll
    for (int o = 128; o > 0; o >>= 1) {
        if (t < o) red[t] += red[t + o];
        __syncthreads();
    }
    if (t == 0) {
        g_partial[blockIdx.x] = red[0];
        __threadfence();
        int old = atomicAdd(&g_count, 1);
        s_last = (old == GATHER_BLOCKS - 1) ? 1 : 0;
    }
    __syncthreads();

    if (s_last) {
        __threadfence();
        float s = 0.f;
        for (int i = t; i < GATHER_BLOCKS; i += 256) s += __ldcg(&g_partial[i]);
        red[t] = s;
        __syncthreads();
#pragma unroll
        for (int o = 128; o > 0; o >>= 1) {
            if (t < o) red[t] += red[t + o];
            __syncthreads();
        }
        if (t == 0) {
            if (out_size >= OUT_FULL) {
                float mse = red[0] / (float)(NTOT * DDIM);
                out[LOSS_OFF] = 1.25f * mse;
            }
            g_count = 0;   // reset for next graph replay
        }
    }
}

// ---------------------------------------------------------------------------
extern "C" void kernel_launch(void* const* d_in, const int* in_sizes, int n_in,
                              void* d_out, int out_size) {
    const float* z   = (const float*)d_in[0];
    const float* cb  = (const float*)d_in[1];
    const float* ema = (const float*)d_in[2];
    float* out = (float*)d_out;

    cudaFuncSetAttribute(vq_coarse_kernel,
                         cudaFuncAttributeMaxDynamicSharedMemorySize, DSMEM);

    vq_convert_kernel<<<(KCB + NTOT) * 32 / 256 + 1, 256>>>(z, cb, ema, out, out_size);
    vq_coarse_kernel<<<NCTA, 256, DSMEM>>>();
    vq_merge_kernel<<<NTOT / 256, 256>>>();
    vq_rescore_kernel<<<NTOT / 8, 256>>>(z, cb);
    vq_gather_kernel<<<GATHER_BLOCKS, 256>>>(z, cb, out, out_size);
}

// round 17
// speedup vs baseline: 1.7915x; 1.7915x over previous
#include <cuda_runtime.h>
#include <cuda_bf16.h>
#include <math.h>
#include <stdint.h>

#define NTOT 16384
#define DDIM 256
#define KCB  8192
#define NCHUNK 64
#define RS_BLOCKS 2048
#define NCAND 8

#define LOSS_OFF (NTOT*DDIM)
#define IDX_OFF  (NTOT*DDIM + 1)
#define PPL_OFF  (NTOT*DDIM + 1 + NTOT)
#define OUT_FULL (NTOT*DDIM + 2 + NTOT)

__device__ __align__(16) uint8_t g_z8[(size_t)NTOT * DDIM];
__device__ __align__(16) uint8_t g_cb8[(size_t)KCB * DDIM];
__device__ float g_e2f[KCB];
__device__ float g_csc[KCB];
__device__ float g_zsc[NTOT];
__device__ int   g_cand[(size_t)NTOT * NCAND];
__device__ float g_partial[RS_BLOCKS];
__device__ int   g_count = 0;

// ---------------------------------------------------------------------------
// helpers
// ---------------------------------------------------------------------------
__device__ __forceinline__ uint32_t smem_u32(const void* p) {
    uint32_t a;
    asm("{ .reg .u64 t; cvta.to.shared.u64 t, %1; cvt.u32.u64 %0, t; }"
        : "=r"(a) : "l"(p));
    return a;
}
#define CP_ASYNC16(dst, src) \
    asm volatile("cp.async.cg.shared.global [%0], [%1], 16;" :: "r"(dst), "l"(src))
#define CP_COMMIT() asm volatile("cp.async.commit_group;" ::: "memory")
#define CP_WAIT(n)  asm volatile("cp.async.wait_group %0;" :: "n"(n) : "memory")

__device__ __forceinline__ void ldsm_x4(uint32_t* r, uint32_t addr) {
    asm volatile("ldmatrix.sync.aligned.m8n8.x4.shared.b16 {%0,%1,%2,%3}, [%4];"
                 : "=r"(r[0]), "=r"(r[1]), "=r"(r[2]), "=r"(r[3]) : "r"(addr));
}
__device__ __forceinline__ void imma16832(int* d, const uint32_t* a,
                                          uint32_t b0, uint32_t b1) {
    asm volatile(
        "mma.sync.aligned.m16n8k32.row.col.s32.s8.s8.s32 "
        "{%0,%1,%2,%3}, {%4,%5,%6,%7}, {%8,%9}, {%0,%1,%2,%3};"
        : "+r"(d[0]), "+r"(d[1]), "+r"(d[2]), "+r"(d[3])
        : "r"(a[0]), "r"(a[1]), "r"(a[2]), "r"(a[3]), "r"(b0), "r"(b1));
}
__device__ __forceinline__ void upd(float& b1, int& i1, float& b2, int& i2,
                                    float d, int code) {
    if (d < b2) {
        if (d < b1) { b2 = b1; i2 = i1; b1 = d; i1 = code; }
        else        { b2 = d; i2 = code; }
    }
}
__device__ __forceinline__ uint32_t pack_s8x4(int q0, int q1, int q2, int q3) {
    return (uint32_t)(q0 & 255) | ((uint32_t)(q1 & 255) << 8)
         | ((uint32_t)(q2 & 255) << 16) | ((uint32_t)(q3 & 255) << 24);
}

// ---------------------------------------------------------------------------
// Kernel 1: per-row int8 quantization of z,cb; exact fp32 e2; last block: ppl
// ---------------------------------------------------------------------------
__global__ void vq_convert_kernel(const float* __restrict__ z,
                                  const float* __restrict__ cb,
                                  const float* __restrict__ ema,
                                  float* __restrict__ out, int out_size) {
    int w    = (blockIdx.x * blockDim.x + threadIdx.x) >> 5;
    int lane = threadIdx.x & 31;
    if (w < KCB) {
        const float4* src = (const float4*)(cb + (size_t)w * DDIM);
        float4 v0 = src[lane * 2], v1 = src[lane * 2 + 1];
        float e2 = v0.x*v0.x + v0.y*v0.y + v0.z*v0.z + v0.w*v0.w
                 + v1.x*v1.x + v1.y*v1.y + v1.z*v1.z + v1.w*v1.w;
        float ma = fmaxf(fmaxf(fmaxf(fabsf(v0.x), fabsf(v0.y)), fmaxf(fabsf(v0.z), fabsf(v0.w))),
                         fmaxf(fmaxf(fabsf(v1.x), fabsf(v1.y)), fmaxf(fabsf(v1.z), fabsf(v1.w))));
#pragma unroll
        for (int o = 16; o > 0; o >>= 1) {
            e2 += __shfl_xor_sync(0xffffffffu, e2, o);
            ma  = fmaxf(ma, __shfl_xor_sync(0xffffffffu, ma, o));
        }
        float inv = 127.f / ma;
        uint2 o8;
        o8.x = pack_s8x4(__float2int_rn(v0.x*inv), __float2int_rn(v0.y*inv),
                         __float2int_rn(v0.z*inv), __float2int_rn(v0.w*inv));
        o8.y = pack_s8x4(__float2int_rn(v1.x*inv), __float2int_rn(v1.y*inv),
                         __float2int_rn(v1.z*inv), __float2int_rn(v1.w*inv));
        ((uint2*)(g_cb8 + (size_t)w * DDIM))[lane] = o8;
        if (lane == 0) { g_e2f[w] = e2; g_csc[w] = ma / 127.f; }
    } else if (w < KCB + NTOT) {
        int r = w - KCB;
        const float4* src = (const float4*)(z + (size_t)r * DDIM);
        float4 v0 = src[lane * 2], v1 = src[lane * 2 + 1];
        float ma = fmaxf(fmaxf(fmaxf(fabsf(v0.x), fabsf(v0.y)), fmaxf(fabsf(v0.z), fabsf(v0.w))),
                         fmaxf(fmaxf(fabsf(v1.x), fabsf(v1.y)), fmaxf(fabsf(v1.z), fabsf(v1.w))));
#pragma unroll
        for (int o = 16; o > 0; o >>= 1)
            ma = fmaxf(ma, __shfl_xor_sync(0xffffffffu, ma, o));
        float inv = 127.f / ma;
        uint2 o8;
        o8.x = pack_s8x4(__float2int_rn(v0.x*inv), __float2int_rn(v0.y*inv),
                         __float2int_rn(v0.z*inv), __float2int_rn(v0.w*inv));
        o8.y = pack_s8x4(__float2int_rn(v1.x*inv), __float2int_rn(v1.y*inv),
                         __float2int_rn(v1.z*inv), __float2int_rn(v1.w*inv));
        ((uint2*)(g_z8 + (size_t)r * DDIM))[lane] = o8;
        if (lane == 0) g_zsc[r] = ma / 127.f;
    } else {
        // perplexity block (depends only on ema)
        __shared__ float r1[256], r2[256];
        const int t = threadIdx.x;
        float sc = 0.f, scl = 0.f;
        for (int k = t; k < KCB; k += 256) {
            float c = ema[k];
            if (k == 2 || k == 3) c = 0.f;
            c = fmaxf(c, 1e-5f);
            sc  += c;
            scl += c * logf(c);
        }
        r1[t] = sc; r2[t] = scl;
        __syncthreads();
#pragma unroll
        for (int o = 128; o > 0; o >>= 1) {
            if (t < o) { r1[t] += r1[t + o]; r2[t] += r2[t + o]; }
            __syncthreads();
        }
        if (t == 0 && out_size >= OUT_FULL) {
            float T = r1[0] + 1e-5f;
            float entropy = logf(T) * (r1[0] / T) - r2[0] / T;
            out[PPL_OFF] = expf(entropy);
        }
    }
}

// ---------------------------------------------------------------------------
// Kernel 2: coarse int8 IMMA GEMM, per-thread-subset top-2 -> top-8/row
// smem: z 32KB @0, cb 2x32KB @32768, e2 2x512 @98304, csc 2x512 @99328
// ---------------------------------------------------------------------------
#define ZS_OFF 0
#define CB_OFF 32768
#define E2_OFF 98304
#define SC_OFF 99328
#define DSMEM  (100352 + 1024)

__device__ __forceinline__ void prefetch_cb(uint32_t sb, int buf, int chunk, int t) {
    const char* csrc = (const char*)(g_cb8 + (size_t)chunk * 128 * DDIM);
    uint32_t cbase = sb + CB_OFF + (uint32_t)buf * 32768u;
#pragma unroll
    for (int i = 0; i < 8; i++) {
        int id = t + i * 256, r = id >> 4, c = id & 15;
        uint32_t dst = cbase + (uint32_t)r * 256u
                     + ((uint32_t)((c & 8) | ((c ^ r) & 7)) << 4);
        CP_ASYNC16(dst, csrc + (size_t)r * 256 + c * 16);
    }
    if (t < 32) {
        uint32_t dst = sb + E2_OFF + (uint32_t)buf * 512u + (uint32_t)t * 16u;
        CP_ASYNC16(dst, (const char*)(g_e2f + chunk * 128) + t * 16);
    } else if (t < 64) {
        int tt = t - 32;
        uint32_t dst = sb + SC_OFF + (uint32_t)buf * 512u + (uint32_t)tt * 16u;
        CP_ASYNC16(dst, (const char*)(g_csc + chunk * 128) + tt * 16);
    }
}

__global__ void __launch_bounds__(256, 1) vq_coarse_kernel() {
    extern __shared__ __align__(16) char dsm[];
    const uint32_t sb = (smem_u32(dsm) + 1023u) & ~1023u;
    const int t  = threadIdx.x;
    const int l  = t & 31;
    const int wid = t >> 5;
    const int wm = wid >> 2, wn = wid & 3;
    const int m0 = blockIdx.x * 128;

    // z tile (128 rows x 256B) + chunk0/1 prefetch
    {
        const char* zsrc = (const char*)(g_z8 + (size_t)m0 * DDIM);
#pragma unroll
        for (int i = 0; i < 8; i++) {
            int id = t + i * 256, r = id >> 4, c = id & 15;
            uint32_t dst = sb + ZS_OFF + (uint32_t)r * 256u
                         + ((uint32_t)((c & 8) | ((c ^ r) & 7)) << 4);
            CP_ASYNC16(dst, zsrc + (size_t)r * 256 + c * 16);
        }
        prefetch_cb(sb, 0, 0, t);
        CP_COMMIT();
        prefetch_cb(sb, 1, 1, t);
        CP_COMMIT();
    }

    // per-thread constant address components
    uint32_t abase[4], ar7[4];
#pragma unroll
    for (int i = 0; i < 4; i++) {
        int ar = wm * 64 + i * 16 + (l & 15);
        abase[i] = sb + ZS_OFF + (uint32_t)ar * 256u;
        ar7[i]   = (uint32_t)(ar & 7);
    }
    const uint32_t ahalf = (uint32_t)(l >> 4);
    uint32_t boff[2], br7[2];
#pragma unroll
    for (int p = 0; p < 2; p++) {
        int br = wn * 32 + p * 16 + ((l >> 4) & 1) * 8 + (l & 7);
        boff[p] = (uint32_t)br * 256u;
        br7[p]  = (uint32_t)(br & 7);
    }
    const uint32_t bhalf = (uint32_t)((l >> 3) & 1);

    // -2 * z row scale for this thread's 8 row-slots
    float szm2[8];
#pragma unroll
    for (int i = 0; i < 4; i++)
#pragma unroll
        for (int h = 0; h < 2; h++) {
            int m = wm * 64 + i * 16 + (l >> 2) + h * 8;
            szm2[i * 2 + h] = -2.f * g_zsc[m0 + m];
        }

    float bd1[8], bd2[8];
    int   bi1[8], bi2[8];
#pragma unroll
    for (int i = 0; i < 8; i++) { bd1[i] = 3.0e38f; bd2[i] = 3.0e38f; bi1[i] = 0; bi2[i] = 0; }

    const int nl0 = wn * 32 + (l & 3) * 2;

    for (int c = 0; c < NCHUNK; c++) {
        const int s = c & 1;
        if (c < NCHUNK - 1) { CP_WAIT(1); } else { CP_WAIT(0); }
        __syncthreads();

        int acc[4][4][4];
#pragma unroll
        for (int i = 0; i < 4; i++)
#pragma unroll
            for (int j = 0; j < 4; j++)
#pragma unroll
                for (int q = 0; q < 4; q++) acc[i][j][q] = 0;

        const uint32_t cbB = sb + CB_OFF + (uint32_t)s * 32768u;
#pragma unroll
        for (int kk = 0; kk < 8; kk++) {           // K = 8 steps x 32 int8
            const uint32_t cA = (uint32_t)(kk * 2) + ahalf;
            const uint32_t swA_hi = (cA & 8u) << 4;
            uint32_t a[4][4];
#pragma unroll
            for (int i = 0; i < 4; i++)
                ldsm_x4(a[i], abase[i] + swA_hi + (((cA ^ ar7[i]) & 7u) << 4));
            const uint32_t cB = (uint32_t)(kk * 2) + bhalf;
            const uint32_t swB_hi = (cB & 8u) << 4;
            uint32_t b[2][4];
#pragma unroll
            for (int p = 0; p < 2; p++)
                ldsm_x4(b[p], cbB + boff[p] + swB_hi + (((cB ^ br7[p]) & 7u) << 4));
#pragma unroll
            for (int i = 0; i < 4; i++)
#pragma unroll
                for (int j = 0; j < 4; j++)
                    imma16832(acc[i][j], a[i], b[j >> 1][(j & 1) * 2], b[j >> 1][(j & 1) * 2 + 1]);
        }

        // epilogue: dist = e2 + (-2 sz sc) * idot, per-subset top-2 (ascending)
        const uint32_t e2b = sb + E2_OFF + (uint32_t)s * 512u;
        const uint32_t scb = sb + SC_OFF + (uint32_t)s * 512u;
#pragma unroll
        for (int j = 0; j < 4; j++) {
            const int nl = nl0 + j * 8;
            float e20, e21, sc0, sc1;
            asm("ld.shared.f32 %0, [%1];" : "=f"(e20) : "r"(e2b + (uint32_t)nl * 4u));
            asm("ld.shared.f32 %0, [%1];" : "=f"(e21) : "r"(e2b + (uint32_t)nl * 4u + 4u));
            asm("ld.shared.f32 %0, [%1];" : "=f"(sc0) : "r"(scb + (uint32_t)nl * 4u));
            asm("ld.shared.f32 %0, [%1];" : "=f"(sc1) : "r"(scb + (uint32_t)nl * 4u + 4u));
            const int code0 = c * 128 + nl, code1 = code0 + 1;
#pragma unroll
            for (int i = 0; i < 4; i++) {
                float d0 = fmaf(szm2[i*2]   * sc0, (float)acc[i][j][0], e20);
                float d1 = fmaf(szm2[i*2]   * sc1, (float)acc[i][j][1], e21);
                float d2 = fmaf(szm2[i*2+1] * sc0, (float)acc[i][j][2], e20);
                float d3 = fmaf(szm2[i*2+1] * sc1, (float)acc[i][j][3], e21);
                upd(bd1[i*2],   bi1[i*2],   bd2[i*2],   bi2[i*2],   d0, code0);
                upd(bd1[i*2],   bi1[i*2],   bd2[i*2],   bi2[i*2],   d1, code1);
                upd(bd1[i*2+1], bi1[i*2+1], bd2[i*2+1], bi2[i*2+1], d2, code0);
                upd(bd1[i*2+1], bi1[i*2+1], bd2[i*2+1], bi2[i*2+1], d3, code1);
            }
        }

        __syncthreads();                     // buf s fully consumed
        if (c + 2 < NCHUNK) { prefetch_cb(sb, s, c + 2, t); CP_COMMIT(); }
    }

    // ---- merge 32 subset-top-2 entries per row -> global top-8 ----
    __syncthreads();
    float* sdm = (float*)(dsm + (sb - smem_u32(dsm)));          // reuse z/cb area
    int*   sim = (int*)(dsm + (sb - smem_u32(dsm)) + 16384);
    const int slot2 = (wn * 4 + (l & 3)) * 2;
#pragma unroll
    for (int i = 0; i < 4; i++) {
#pragma unroll
        for (int h = 0; h < 2; h++) {
            int m = wm * 64 + i * 16 + (l >> 2) + h * 8;
            sdm[m * 32 + slot2]     = bd1[i * 2 + h];
            sim[m * 32 + slot2]     = bi1[i * 2 + h];
            sdm[m * 32 + slot2 + 1] = bd2[i * 2 + h];
            sim[m * 32 + slot2 + 1] = bi2[i * 2 + h];
        }
    }
    __syncthreads();
    if (t < 128) {
        float td[NCAND]; int ti[NCAND];
#pragma unroll
        for (int q = 0; q < NCAND; q++) { td[q] = 3.0e38f; ti[q] = 0x7fffffff; }
        for (int e = 0; e < 32; e++) {
            float d = sdm[t * 32 + e];
            int  ix = sim[t * 32 + e];
            if (d < td[NCAND-1] || (d == td[NCAND-1] && ix < ti[NCAND-1])) {
                int pos = NCAND - 1;
                while (pos > 0 && (d < td[pos-1] || (d == td[pos-1] && ix < ti[pos-1]))) {
                    td[pos] = td[pos-1]; ti[pos] = ti[pos-1]; pos--;
                }
                td[pos] = d; ti[pos] = ix;
            }
        }
#pragma unroll
        for (int q = 0; q < NCAND; q++)
            g_cand[(size_t)(m0 + t) * NCAND + q] = ti[q];
    }
}

// ---------------------------------------------------------------------------
// Kernel 3: exact fp32 rescore + gather + loss. Warp per row, 8 rows/block.
// bd of winner IS sum((z_q - z)^2) for the row -> loss for free.
// ---------------------------------------------------------------------------
__global__ void __launch_bounds__(256) vq_rescore_kernel(const float* __restrict__ z,
                                                         const float* __restrict__ cb,
                                                         float* __restrict__ out,
                                                         int out_size) {
    __shared__ __align__(16) float zs[8 * 256];
    __shared__ float s_bd[8];
    __shared__ float red[256];
    __shared__ int   s_last;
    const int t  = threadIdx.x;
    const int w  = t >> 5;
    const int l  = t & 31;
    const int r0 = blockIdx.x * 8;

    {
        const float4* src = (const float4*)(z + (size_t)r0 * DDIM);
        float4* dst = (float4*)zs;
        dst[t]       = src[t];
        dst[t + 256] = src[t + 256];
    }
    __syncthreads();

    const int row  = r0 + w;
    const int cand = g_cand[(size_t)row * NCAND + (l >> 2)];
    const int sub  = l & 3;
    const float4* cr = (const float4*)(cb + (size_t)cand * DDIM);
    const float*  zr = zs + w * 256;
    float s = 0.f;
#pragma unroll
    for (int k = 0; k < 16; k++) {
        int d4 = k * 4 + sub;
        float4 cv = cr[d4];
        float4 zv = *(const float4*)(zr + d4 * 4);
        float dx = zv.x - cv.x, dy = zv.y - cv.y, dz = zv.z - cv.z, dw = zv.w - cv.w;
        s += dx * dx + dy * dy + dz * dz + dw * dw;
    }
    s += __shfl_xor_sync(0xffffffffu, s, 1);
    s += __shfl_xor_sync(0xffffffffu, s, 2);

    float bd = 3.0e38f; int bi = 0x7fffffff;
#pragma unroll
    for (int q = 0; q < NCAND; q++) {
        float d  = __shfl_sync(0xffffffffu, s, q * 4);
        int   ix = __shfl_sync(0xffffffffu, cand, q * 4);
        if (d < bd || (d == bd && ix < bi)) { bd = d; bi = ix; }
    }

    // gather: copy cb[bi] row -> out (2 float4 per lane)
    {
        const float4* src = (const float4*)(cb + (size_t)bi * DDIM);
        float4* dst = (float4*)(out + (size_t)row * DDIM);
        dst[l]      = src[l];
        dst[l + 32] = src[l + 32];
    }
    if (l == 0) {
        if (out_size >= OUT_FULL) out[IDX_OFF + row] = (float)bi;
        s_bd[w] = bd;
    }
    __syncthreads();

    // per-block loss partial (fixed order), then last-block final reduce
    if (t == 0) {
        float p = 0.f;
#pragma unroll
        for (int i = 0; i < 8; i++) p += s_bd[i];
        g_partial[blockIdx.x] = p;
        __threadfence();
        int old = atomicAdd(&g_count, 1);
        s_last = (old == RS_BLOCKS - 1) ? 1 : 0;
    }
    __syncthreads();

    if (s_last) {
        __threadfence();
        float p = 0.f;
        for (int i = t; i < RS_BLOCKS; i += 256) p += __ldcg(&g_partial[i]);
        red[t] = p;
        __syncthreads();
#pragma unroll
        for (int o = 128; o > 0; o >>= 1) {
            if (t < o) red[t] += red[t + o];
            __syncthreads();
        }
        if (t == 0) {
            if (out_size >= OUT_FULL) {
                float mse = red[0] / (float)(NTOT * DDIM);
                out[LOSS_OFF] = 1.25f * mse;
            }
            g_count = 0;   // reset for next graph replay
        }
    }
}

// ---------------------------------------------------------------------------
extern "C" void kernel_launch(void* const* d_in, const int* in_sizes, int n_in,
                              void* d_out, int out_size) {
    const float* z   = (const float*)d_in[0];
    const float* cb  = (const float*)d_in[1];
    const float* ema = (const float*)d_in[2];
    float* out = (float*)d_out;

    cudaFuncSetAttribute(vq_coarse_kernel,
                         cudaFuncAttributeMaxDynamicSharedMemorySize, DSMEM);

    vq_convert_kernel<<<(KCB + NTOT) * 32 / 256 + 1, 256>>>(z, cb, ema, out, out_size);
    vq_coarse_kernel<<<NTOT / 128, 256, DSMEM>>>();
    vq_rescore_kernel<<<RS_BLOCKS, 256>>>(z, cb, out, out_size);
}